// round 13
// baseline (speedup 1.0000x reference)
#include <cuda_runtime.h>
#include <cuda_fp16.h>
#include <cstdint>

#define BATCH 16384
#define HID   512
#define KDIM  1024
#define NDIM  2048

#define BM 128
#define BN 128
#define BK 64
#define NST 3
#define KBLK (KDIM / BK)          // 16
#define TPB 512
#define ROWB 128                  // 64 halfs = 128B row, XOR-swizzled (no pad)
#define STAGE_A (BM * ROWB)       // 16384
#define STAGE_B (BN * ROWB)       // 16384
#define STAGE_BYTES (STAGE_A + STAGE_B)      // 32768
#define SMEM_DYN (NST * STAGE_BYTES)         // 98304

// fp16 scratch (static device arrays: allocation-free)
__device__ __half g_xh[(size_t)BATCH * KDIM];   // [B,1024] = [x | h_prev]
__device__ __half g_w [(size_t)NDIM * KDIM];    // [2048,1024], rows interleaved: n' = 4h+gate

// ---------------------------------------------------------------- helpers
__device__ __forceinline__ uint32_t smem_u32(const void* p) {
    uint32_t a;
    asm("{ .reg .u64 t; cvta.to.shared.u64 t, %1; cvt.u32.u64 %0, t; }" : "=r"(a) : "l"(p));
    return a;
}
__device__ __forceinline__ void ldsm4(uint32_t* r, uint32_t addr) {
    asm volatile("ldmatrix.sync.aligned.m8n8.x4.shared.b16 {%0,%1,%2,%3}, [%4];"
                 : "=r"(r[0]), "=r"(r[1]), "=r"(r[2]), "=r"(r[3]) : "r"(addr));
}
__device__ __forceinline__ void mma16816(float* d, const uint32_t* a, const uint32_t* b) {
    asm volatile("mma.sync.aligned.m16n8k16.row.col.f32.f16.f16.f32 "
                 "{%0,%1,%2,%3}, {%4,%5,%6,%7}, {%8,%9}, {%0,%1,%2,%3};"
                 : "+f"(d[0]), "+f"(d[1]), "+f"(d[2]), "+f"(d[3])
                 : "r"(a[0]), "r"(a[1]), "r"(a[2]), "r"(a[3]), "r"(b[0]), "r"(b[1]));
}
__device__ __forceinline__ float sigmoid_f(float x) {
    return 1.0f / (1.0f + __expf(-x));
}
__device__ __forceinline__ float tanh_f(float x) {
    x = fminf(fmaxf(x, -15.0f), 15.0f);
    float t = __expf(2.0f * x);
    return __fdividef(t - 1.0f, t + 1.0f);
}
__device__ __forceinline__ uint32_t pk(float a, float b) {
    __half2 h = __floats2half2_rn(a, b);
    return *reinterpret_cast<uint32_t*>(&h);
}

// ---------------------------------------------------------------- single pack kernel
// A part: 2M items (BATCH*KDIM/8), W part: 256K items (NDIM*KDIM/8). 8 floats/thread.
#define A_ITEMS (BATCH * KDIM / 8)
#define W_ITEMS (NDIM * KDIM / 8)
__global__ void pack_all(const float* __restrict__ x, const float* __restrict__ h,
                         const float* __restrict__ w_ih, const float* __restrict__ w_hh) {
    int idx = blockIdx.x * blockDim.x + threadIdx.x;
    const float* src;
    __half* dst;
    if (idx < A_ITEMS) {
        int m = idx >> 7;                 // 128 8-float chunks per row
        int k8 = (idx & 127) << 3;
        src = (k8 < 512) ? x + (size_t)m * 512 + k8
                         : h + (size_t)m * 512 + (k8 - 512);
        dst = g_xh + (size_t)m * KDIM + k8;
    } else {
        int j = idx - A_ITEMS;
        if (j >= W_ITEMS) return;
        int np = j >> 7;                  // interleaved row n' = 4h + gate
        int k8 = (j & 127) << 3;
        int g = np & 3, hh = np >> 2;
        int srow = g * 512 + hh;
        src = (k8 < 512) ? w_ih + (size_t)srow * 512 + k8
                         : w_hh + (size_t)srow * 512 + (k8 - 512);
        dst = g_w + (size_t)np * KDIM + k8;
    }
    float4 v0 = ((const float4*)src)[0];
    float4 v1 = ((const float4*)src)[1];
    uint4 u;
    u.x = pk(v0.x, v0.y);
    u.y = pk(v0.z, v0.w);
    u.z = pk(v1.x, v1.y);
    u.w = pk(v1.z, v1.w);
    *reinterpret_cast<uint4*>(dst) = u;
}

// ---------------------------------------------------------------- fused GEMM + LSTM
__global__ void __launch_bounds__(TPB, 2)
lstm_gemm(const float* __restrict__ c_prev, float* __restrict__ out,
          const float* __restrict__ b_ih, const float* __restrict__ b_hh) {
    extern __shared__ __align__(16) char dyn[];
    __shared__ float s_bias[BN];

    const int tid = threadIdx.x;
    const int wid = tid >> 5;
    const int lid = tid & 31;
    const int mw = wid >> 2;          // 0..3 : warp M index (32 rows each)
    const int nw = wid & 3;           // 0..3 : warp N index (32 cols each)
    const int m0 = blockIdx.y * BM;
    const int n0 = blockIdx.x * BN;
    const int h0g = n0 >> 2;          // 32 hidden units per CTA

    const uint32_t dynbase = smem_u32(dyn);

    // fused bias: interleaved n' = 4h + gate
    if (tid < BN) {
        int np = n0 + tid;
        int g = np & 3, hh = np >> 2;
        s_bias[tid] = b_ih[g * 512 + hh] + b_hh[g * 512 + hh];
    }

    float acc[2][4][4];               // [mt 16-rows][nt 8-cols][frag] : 32x32 warp tile
    #pragma unroll
    for (int a = 0; a < 2; a++)
        #pragma unroll
        for (int b = 0; b < 4; b++)
            #pragma unroll
            for (int c = 0; c < 4; c++) acc[a][b][c] = 0.0f;

    // -------- per-thread loader: 2 A chunks + 2 B chunks of 16B per stage
    const int lrow = tid >> 3;        // 0..63
    const int lcc  = tid & 7;         // c16 index 0..7
    const int lswz = (lcc ^ (lrow & 7)) << 4;    // XOR swizzle (row+64 has same low3)
    const __half* gA = g_xh + (size_t)(m0 + lrow) * KDIM + lcc * 8;
    const __half* gB = g_w  + (size_t)(n0 + lrow) * KDIM + lcc * 8;
    const uint32_t sa = dynbase + lrow * ROWB + lswz;
    const uint32_t sb = sa + STAGE_A;
    const size_t GROW64 = (size_t)64 * KDIM;     // +64 rows in gmem

    #define LOAD_STAGE(OFS)                                                     \
        do {                                                                    \
            asm volatile("cp.async.cg.shared.global [%0], [%1], 16;"            \
                         :: "r"(sa + (OFS)), "l"(gA));                          \
            asm volatile("cp.async.cg.shared.global [%0], [%1], 16;"            \
                         :: "r"(sa + 64 * ROWB + (OFS)), "l"(gA + GROW64));     \
            asm volatile("cp.async.cg.shared.global [%0], [%1], 16;"            \
                         :: "r"(sb + (OFS)), "l"(gB));                          \
            asm volatile("cp.async.cg.shared.global [%0], [%1], 16;"            \
                         :: "r"(sb + 64 * ROWB + (OFS)), "l"(gB + GROW64));     \
            gA += BK; gB += BK;                                                 \
        } while (0)

    // per-warp ldsm addressing: swizzled k16 offsets hoisted out of the loop
    const int arow = mw * 32 + (lid & 15);
    const uint32_t abase = dynbase + arow * ROWB;
    const int rxa = arow & 7;
    const int hia = lid >> 4;                    // col16 half
    const int bg = lid >> 3, br = lid & 7;
    const int brow = nw * 32 + (bg >> 1) * 8 + br;
    const uint32_t bbase = dynbase + STAGE_A + brow * ROWB;
    const int rxb = br;
    const int hib = bg & 1;
    uint32_t axo[4], bxo[4];
    #pragma unroll
    for (int q = 0; q < 4; q++) {
        axo[q] = (uint32_t)(((2 * q + hia) ^ rxa) << 4);
        bxo[q] = (uint32_t)(((2 * q + hib) ^ rxb) << 4);
    }

    auto compute_q = [&](uint32_t sofs, int q) {
        uint32_t afr[2][4];
        #pragma unroll
        for (int mt = 0; mt < 2; mt++)
            ldsm4(afr[mt], abase + sofs + mt * (16 * ROWB) + axo[q]);
        uint32_t bfr[2][4];
        #pragma unroll
        for (int np = 0; np < 2; np++)
            ldsm4(bfr[np], bbase + sofs + np * (16 * ROWB) + bxo[q]);
        #pragma unroll
        for (int mt = 0; mt < 2; mt++)
            #pragma unroll
            for (int np = 0; np < 2; np++) {
                mma16816(acc[mt][2 * np],     afr[mt], &bfr[np][0]);
                mma16816(acc[mt][2 * np + 1], afr[mt], &bfr[np][2]);
            }
    };

    // prologue: prefetch NST-1 stages
    LOAD_STAGE(0);
    asm volatile("cp.async.commit_group;" ::: "memory");
    LOAD_STAGE(STAGE_BYTES);
    asm volatile("cp.async.commit_group;" ::: "memory");

    // epilogue c_prev tile lives in pipeline slot 1 (free from kb=KBLK-2 on),
    // 36-float rows (144B, 16B-aligned) for cp.async
    const uint32_t c_base = dynbase + STAGE_BYTES;

    // main K loop — one barrier per iteration; gmem loads overlap compute
    uint32_t scur = 0, sload = 2 * STAGE_BYTES;
    for (int kb = 0; kb < KBLK; kb++) {
        asm volatile("cp.async.wait_group %0;" :: "n"(NST - 2) : "memory");
        __syncthreads();
        if (kb + NST - 1 < KBLK) {
            LOAD_STAGE(sload);
            sload += STAGE_BYTES;
            if (sload == NST * STAGE_BYTES) sload = 0;
        } else if (kb == KBLK - 2) {
            // prefetch c_prev into slot 1 (overlaps last two K-steps)
            #pragma unroll
            for (int i = 0; i < 2; i++) {
                int idx = tid + i * TPB;         // 0..1023
                int r = idx >> 3, c16 = idx & 7;
                uint32_t saddr = c_base + r * 144 + c16 * 16;
                const float* gaddr = c_prev + (size_t)(m0 + r) * HID + h0g + c16 * 4;
                asm volatile("cp.async.cg.shared.global [%0], [%1], 16;"
                             :: "r"(saddr), "l"(gaddr));
            }
        }
        asm volatile("cp.async.commit_group;" ::: "memory");
        compute_q(scur, 0);
        compute_q(scur, 1);
        compute_q(scur, 2);
        compute_q(scur, 3);
        scur += STAGE_BYTES;
        if (scur == NST * STAGE_BYTES) scur = 0;
    }

    // drain c_prev prefetch; all MMAs done
    asm volatile("cp.async.wait_group 0;" ::: "memory");
    __syncthreads();

    // -------- fused LSTM epilogue
    float* c_tile = (float*)(dyn + STAGE_BYTES);          // [128][36] (slot 1)
    float* hstage = (float*)dyn;                          // [128][33] (slot 0)
    float* cstage = (float*)(dyn + 2 * STAGE_BYTES);      // [128][33] (slot 2)
    const int odd = lid & 1;

    #pragma unroll
    for (int mt = 0; mt < 2; mt++) {
        const int r0 = mw * 32 + mt * 16 + (lid >> 2);
        const int rme = r0 + (odd << 3);          // even lane: r0; odd lane: r0+8
        #pragma unroll
        for (int nt = 0; nt < 4; nt++) {
            int ncol = nw * 32 + nt * 8 + 2 * (lid & 3);
            float b0 = s_bias[ncol], b1 = s_bias[ncol + 1];
            float v00 = acc[mt][nt][0] + b0;     // row r0,   col ncol
            float v01 = acc[mt][nt][1] + b1;     // row r0,   col ncol+1
            float v10 = acc[mt][nt][2] + b0;     // row r0+8, col ncol
            float v11 = acc[mt][nt][3] + b1;     // row r0+8, col ncol+1
            // even lane holds (i,f); odd lane holds (g,o) of the same hidden unit
            float w00 = __shfl_xor_sync(0xffffffffu, v00, 1);
            float w01 = __shfl_xor_sync(0xffffffffu, v01, 1);
            float w10 = __shfl_xor_sync(0xffffffffu, v10, 1);
            float w11 = __shfl_xor_sync(0xffffffffu, v11, 1);
            // even lane computes row r0: i=v00 f=v01 g=w00 o=w01
            // odd  lane computes row r0+8: i=w10 f=w11 g=v10 o=v11
            float gi = odd ? w10 : v00;
            float gf = odd ? w11 : v01;
            float gg = odd ? v10 : w00;
            float go = odd ? v11 : w01;
            int hl = ncol >> 2;
            float ia = sigmoid_f(gi), fa = sigmoid_f(gf);
            float ga = tanh_f(gg),    oa = sigmoid_f(go);
            float cp = c_tile[rme * 36 + hl];
            float cn = fa * cp + ia * ga;
            cstage[rme * 33 + hl] = cn;
            hstage[rme * 33 + hl] = oa * tanh_f(cn);
        }
    }
    __syncthreads();

    // coalesced writeout: h_new then c_new (128B segments per row)
    for (int i = tid; i < 128 * 32; i += TPB) {
        int r = i >> 5, hh = i & 31;
        size_t go = (size_t)(m0 + r) * HID + h0g + hh;
        out[go] = hstage[r * 33 + hh];
        out[(size_t)BATCH * HID + go] = cstage[r * 33 + hh];
    }
}

// ---------------------------------------------------------------- launch
extern "C" void kernel_launch(void* const* d_in, const int* in_sizes, int n_in,
                              void* d_out, int out_size) {
    const float* x      = (const float*)d_in[0];
    const float* h_prev = (const float*)d_in[1];
    const float* c_prev = (const float*)d_in[2];
    const float* w_ih   = (const float*)d_in[3];
    const float* w_hh   = (const float*)d_in[4];
    const float* b_ih   = (const float*)d_in[5];
    const float* b_hh   = (const float*)d_in[6];
    float* out = (float*)d_out;

    pack_all<<<(A_ITEMS + W_ITEMS + 255) / 256, 256>>>(x, h_prev, w_ih, w_hh);

    cudaFuncSetAttribute(lstm_gemm, cudaFuncAttributeMaxDynamicSharedMemorySize, SMEM_DYN);
    dim3 grid(NDIM / BN, BATCH / BM);   // (16, 128)
    lstm_gemm<<<grid, TPB, SMEM_DYN>>>(c_prev, out, b_ih, b_hh);
}

// round 15
// speedup vs baseline: 1.6446x; 1.6446x over previous
#include <cuda_runtime.h>
#include <cuda_fp16.h>
#include <cstdint>

#define BATCH 16384
#define HID   512
#define KDIM  1024
#define NDIM  2048

#define BM 128
#define BN 128
#define BK 64
#define NST 3
#define KBLK (KDIM / BK)          // 16
#define TPB 512
#define ROWB 128                  // 64 halfs = 128B row, XOR-swizzled (no pad)
#define STAGE_A (BM * ROWB)       // 16384
#define STAGE_B (BN * ROWB)       // 16384
#define STAGE_BYTES (STAGE_A + STAGE_B)      // 32768
#define SMEM_DYN (NST * STAGE_BYTES)         // 98304

// fp16 scratch (static device arrays: allocation-free)
__device__ __half g_xh[(size_t)BATCH * KDIM];   // [B,1024] = [x | h_prev]
__device__ __half g_w [(size_t)NDIM * KDIM];    // [2048,1024], rows interleaved: n' = 4h+gate

// ---------------------------------------------------------------- helpers
__device__ __forceinline__ uint32_t smem_u32(const void* p) {
    uint32_t a;
    asm("{ .reg .u64 t; cvta.to.shared.u64 t, %1; cvt.u32.u64 %0, t; }" : "=r"(a) : "l"(p));
    return a;
}
__device__ __forceinline__ void ldsm4(uint32_t* r, uint32_t addr) {
    asm volatile("ldmatrix.sync.aligned.m8n8.x4.shared.b16 {%0,%1,%2,%3}, [%4];"
                 : "=r"(r[0]), "=r"(r[1]), "=r"(r[2]), "=r"(r[3]) : "r"(addr));
}
__device__ __forceinline__ void mma16816(float* d, const uint32_t* a, const uint32_t* b) {
    asm volatile("mma.sync.aligned.m16n8k16.row.col.f32.f16.f16.f32 "
                 "{%0,%1,%2,%3}, {%4,%5,%6,%7}, {%8,%9}, {%0,%1,%2,%3};"
                 : "+f"(d[0]), "+f"(d[1]), "+f"(d[2]), "+f"(d[3])
                 : "r"(a[0]), "r"(a[1]), "r"(a[2]), "r"(a[3]), "r"(b[0]), "r"(b[1]));
}
__device__ __forceinline__ float sigmoid_f(float x) {
    return 1.0f / (1.0f + __expf(-x));
}
__device__ __forceinline__ float tanh_f(float x) {
    x = fminf(fmaxf(x, -15.0f), 15.0f);
    float t = __expf(2.0f * x);
    return __fdividef(t - 1.0f, t + 1.0f);
}
__device__ __forceinline__ uint32_t pk(float a, float b) {
    __half2 h = __floats2half2_rn(a, b);
    return *reinterpret_cast<uint32_t*>(&h);
}

// ---------------------------------------------------------------- single pack kernel
// A part: 2M items (BATCH*KDIM/8), W part: 256K items (NDIM*KDIM/8). 8 floats/thread.
#define A_ITEMS (BATCH * KDIM / 8)
#define W_ITEMS (NDIM * KDIM / 8)
__global__ void pack_all(const float* __restrict__ x, const float* __restrict__ h,
                         const float* __restrict__ w_ih, const float* __restrict__ w_hh) {
    int idx = blockIdx.x * blockDim.x + threadIdx.x;
    const float* src;
    __half* dst;
    if (idx < A_ITEMS) {
        int m = idx >> 7;                 // 128 8-float chunks per row
        int k8 = (idx & 127) << 3;
        src = (k8 < 512) ? x + (size_t)m * 512 + k8
                         : h + (size_t)m * 512 + (k8 - 512);
        dst = g_xh + (size_t)m * KDIM + k8;
    } else {
        int j = idx - A_ITEMS;
        if (j >= W_ITEMS) return;
        int np = j >> 7;                  // interleaved row n' = 4h + gate
        int k8 = (j & 127) << 3;
        int g = np & 3, hh = np >> 2;
        int srow = g * 512 + hh;
        src = (k8 < 512) ? w_ih + (size_t)srow * 512 + k8
                         : w_hh + (size_t)srow * 512 + (k8 - 512);
        dst = g_w + (size_t)np * KDIM + k8;
    }
    float4 v0 = ((const float4*)src)[0];
    float4 v1 = ((const float4*)src)[1];
    uint4 u;
    u.x = pk(v0.x, v0.y);
    u.y = pk(v0.z, v0.w);
    u.z = pk(v1.x, v1.y);
    u.w = pk(v1.z, v1.w);
    *reinterpret_cast<uint4*>(dst) = u;
}

// ---------------------------------------------------------------- fused GEMM + LSTM
__global__ void __launch_bounds__(TPB, 2)
lstm_gemm(const float* __restrict__ c_prev, float* __restrict__ out,
          const float* __restrict__ b_ih, const float* __restrict__ b_hh) {
    extern __shared__ __align__(16) char dyn[];
    __shared__ float s_bias[BN];

    const int tid = threadIdx.x;
    const int wid = tid >> 5;
    const int lid = tid & 31;
    const int mw = wid >> 2;          // 0..3 : warp M index (32 rows each)
    const int nw = wid & 3;           // 0..3 : warp N index (32 cols each)
    const int m0 = blockIdx.y * BM;
    const int n0 = blockIdx.x * BN;
    const int h0g = n0 >> 2;          // 32 hidden units per CTA

    const uint32_t dynbase = smem_u32(dyn);

    // fused bias: interleaved n' = 4h + gate
    if (tid < BN) {
        int np = n0 + tid;
        int g = np & 3, hh = np >> 2;
        s_bias[tid] = b_ih[g * 512 + hh] + b_hh[g * 512 + hh];
    }

    float acc[2][4][4];               // [mt 16-rows][nt 8-cols][frag] : 32x32 warp tile
    #pragma unroll
    for (int a = 0; a < 2; a++)
        #pragma unroll
        for (int b = 0; b < 4; b++)
            #pragma unroll
            for (int c = 0; c < 4; c++) acc[a][b][c] = 0.0f;

    // -------- per-thread loader: 2 A chunks + 2 B chunks of 16B per stage
    const int lrow = tid >> 3;        // 0..63
    const int lcc  = tid & 7;         // c16 index 0..7
    const int lswz = (lcc ^ (lrow & 7)) << 4;    // XOR swizzle (row+64 has same low3)
    const __half* gA = g_xh + (size_t)(m0 + lrow) * KDIM + lcc * 8;
    const __half* gB = g_w  + (size_t)(n0 + lrow) * KDIM + lcc * 8;
    const uint32_t sa = dynbase + lrow * ROWB + lswz;
    const uint32_t sb = sa + STAGE_A;
    const size_t GROW64 = (size_t)64 * KDIM;     // +64 rows in gmem

    #define LOAD_STAGE(OFS)                                                     \
        do {                                                                    \
            asm volatile("cp.async.cg.shared.global [%0], [%1], 16;"            \
                         :: "r"(sa + (OFS)), "l"(gA));                          \
            asm volatile("cp.async.cg.shared.global [%0], [%1], 16;"            \
                         :: "r"(sa + 64 * ROWB + (OFS)), "l"(gA + GROW64));     \
            asm volatile("cp.async.cg.shared.global [%0], [%1], 16;"            \
                         :: "r"(sb + (OFS)), "l"(gB));                          \
            asm volatile("cp.async.cg.shared.global [%0], [%1], 16;"            \
                         :: "r"(sb + 64 * ROWB + (OFS)), "l"(gB + GROW64));     \
            gA += BK; gB += BK;                                                 \
        } while (0)

    // per-warp ldsm addressing (XOR swizzle applied inline per k16-quarter q:
    // q is a literal at every call site, so the offset folds — NO indexed arrays,
    // which spill at the 64-reg cap)
    const int arow = mw * 32 + (lid & 15);
    const uint32_t abase = dynbase + arow * ROWB;
    const int rxa = arow & 7;
    const int hia = lid >> 4;                    // col16 half
    const int bg = lid >> 3, br = lid & 7;
    const int brow = nw * 32 + (bg >> 1) * 8 + br;
    const uint32_t bbase = dynbase + STAGE_A + brow * ROWB;
    const int rxb = br;
    const int hib = bg & 1;

    auto compute_q = [&](uint32_t sofs, int q) {
        uint32_t afr[2][4];
        #pragma unroll
        for (int mt = 0; mt < 2; mt++)
            ldsm4(afr[mt], abase + sofs + mt * (16 * ROWB) + (((2 * q + hia) ^ rxa) << 4));
        uint32_t bfr[2][4];
        #pragma unroll
        for (int np = 0; np < 2; np++)
            ldsm4(bfr[np], bbase + sofs + np * (16 * ROWB) + (((2 * q + hib) ^ rxb) << 4));
        #pragma unroll
        for (int mt = 0; mt < 2; mt++)
            #pragma unroll
            for (int np = 0; np < 2; np++) {
                mma16816(acc[mt][2 * np],     afr[mt], &bfr[np][0]);
                mma16816(acc[mt][2 * np + 1], afr[mt], &bfr[np][2]);
            }
    };

    // prologue: prefetch NST-1 stages
    LOAD_STAGE(0);
    asm volatile("cp.async.commit_group;" ::: "memory");
    LOAD_STAGE(STAGE_BYTES);
    asm volatile("cp.async.commit_group;" ::: "memory");

    // epilogue c_prev tile lives in pipeline slot 1 (free from kb=KBLK-2 on),
    // 36-float rows (144B, 16B-aligned) for cp.async
    const uint32_t c_base = dynbase + STAGE_BYTES;

    // main K loop — one barrier per iteration; gmem loads overlap compute
    uint32_t scur = 0, sload = 2 * STAGE_BYTES;
    for (int kb = 0; kb < KBLK; kb++) {
        asm volatile("cp.async.wait_group %0;" :: "n"(NST - 2) : "memory");
        __syncthreads();
        if (kb + NST - 1 < KBLK) {
            LOAD_STAGE(sload);
            sload += STAGE_BYTES;
            if (sload == NST * STAGE_BYTES) sload = 0;
        } else if (kb == KBLK - 2) {
            // prefetch c_prev into slot 1 (overlaps last two K-steps)
            #pragma unroll
            for (int i = 0; i < 2; i++) {
                int idx = tid + i * TPB;         // 0..1023
                int r = idx >> 3, c16 = idx & 7;
                uint32_t saddr = c_base + r * 144 + c16 * 16;
                const float* gaddr = c_prev + (size_t)(m0 + r) * HID + h0g + c16 * 4;
                asm volatile("cp.async.cg.shared.global [%0], [%1], 16;"
                             :: "r"(saddr), "l"(gaddr));
            }
        }
        asm volatile("cp.async.commit_group;" ::: "memory");
        compute_q(scur, 0);
        compute_q(scur, 1);
        compute_q(scur, 2);
        compute_q(scur, 3);
        scur += STAGE_BYTES;
        if (scur == NST * STAGE_BYTES) scur = 0;
    }

    // drain c_prev prefetch; all MMAs done
    asm volatile("cp.async.wait_group 0;" ::: "memory");
    __syncthreads();

    // -------- fused LSTM epilogue
    float* c_tile = (float*)(dyn + STAGE_BYTES);          // [128][36] (slot 1)
    float* hstage = (float*)dyn;                          // [128][33] (slot 0)
    float* cstage = (float*)(dyn + 2 * STAGE_BYTES);      // [128][33] (slot 2)
    const int odd = lid & 1;

    #pragma unroll
    for (int mt = 0; mt < 2; mt++) {
        const int r0 = mw * 32 + mt * 16 + (lid >> 2);
        const int rme = r0 + (odd << 3);          // even lane: r0; odd lane: r0+8
        #pragma unroll
        for (int nt = 0; nt < 4; nt++) {
            int ncol = nw * 32 + nt * 8 + 2 * (lid & 3);
            float b0 = s_bias[ncol], b1 = s_bias[ncol + 1];
            float v00 = acc[mt][nt][0] + b0;     // row r0,   col ncol
            float v01 = acc[mt][nt][1] + b1;     // row r0,   col ncol+1
            float v10 = acc[mt][nt][2] + b0;     // row r0+8, col ncol
            float v11 = acc[mt][nt][3] + b1;     // row r0+8, col ncol+1
            // even lane holds (i,f); odd lane holds (g,o) of the same hidden unit
            float w00 = __shfl_xor_sync(0xffffffffu, v00, 1);
            float w01 = __shfl_xor_sync(0xffffffffu, v01, 1);
            float w10 = __shfl_xor_sync(0xffffffffu, v10, 1);
            float w11 = __shfl_xor_sync(0xffffffffu, v11, 1);
            // even lane computes row r0: i=v00 f=v01 g=w00 o=w01
            // odd  lane computes row r0+8: i=w10 f=w11 g=v10 o=v11
            float gi = odd ? w10 : v00;
            float gf = odd ? w11 : v01;
            float gg = odd ? v10 : w00;
            float go = odd ? v11 : w01;
            int hl = ncol >> 2;
            float ia = sigmoid_f(gi), fa = sigmoid_f(gf);
            float ga = tanh_f(gg),    oa = sigmoid_f(go);
            float cp = c_tile[rme * 36 + hl];
            float cn = fa * cp + ia * ga;
            cstage[rme * 33 + hl] = cn;
            hstage[rme * 33 + hl] = oa * tanh_f(cn);
        }
    }
    __syncthreads();

    // coalesced writeout: h_new then c_new (128B segments per row)
    for (int i = tid; i < 128 * 32; i += TPB) {
        int r = i >> 5, hh = i & 31;
        size_t go = (size_t)(m0 + r) * HID + h0g + hh;
        out[go] = hstage[r * 33 + hh];
        out[(size_t)BATCH * HID + go] = cstage[r * 33 + hh];
    }
}

// ---------------------------------------------------------------- launch
extern "C" void kernel_launch(void* const* d_in, const int* in_sizes, int n_in,
                              void* d_out, int out_size) {
    const float* x      = (const float*)d_in[0];
    const float* h_prev = (const float*)d_in[1];
    const float* c_prev = (const float*)d_in[2];
    const float* w_ih   = (const float*)d_in[3];
    const float* w_hh   = (const float*)d_in[4];
    const float* b_ih   = (const float*)d_in[5];
    const float* b_hh   = (const float*)d_in[6];
    float* out = (float*)d_out;

    pack_all<<<(A_ITEMS + W_ITEMS + 255) / 256, 256>>>(x, h_prev, w_ih, w_hh);

    cudaFuncSetAttribute(lstm_gemm, cudaFuncAttributeMaxDynamicSharedMemorySize, SMEM_DYN);
    dim3 grid(NDIM / BN, BATCH / BM);   // (16, 128)
    lstm_gemm<<<grid, TPB, SMEM_DYN>>>(c_prev, out, b_ih, b_hh);
}

// round 16
// speedup vs baseline: 1.6766x; 1.0195x over previous
#include <cuda_runtime.h>
#include <cuda_fp16.h>
#include <cstdint>

#define BATCH 16384
#define HID   512
#define KDIM  1024
#define NDIM  2048

#define BM 128
#define BN 128
#define BK 64
#define NST 3
#define KBLK (KDIM / BK)          // 16
#define TPB 512
#define ROWB 128                  // 64 halfs = 128B row, XOR-swizzled (no pad)
#define STAGE_A (BM * ROWB)       // 16384
#define STAGE_B (BN * ROWB)       // 16384
#define STAGE_BYTES (STAGE_A + STAGE_B)      // 32768
#define SMEM_DYN (NST * STAGE_BYTES)         // 98304

// fp16 scratch (static device arrays: allocation-free)
__device__ __half g_xh[(size_t)BATCH * KDIM];   // [B,1024] = [x | h_prev]
__device__ __half g_w [(size_t)NDIM * KDIM];    // [2048,1024], rows interleaved: n' = 4h+gate

// ---------------------------------------------------------------- helpers
__device__ __forceinline__ uint32_t smem_u32(const void* p) {
    uint32_t a;
    asm("{ .reg .u64 t; cvta.to.shared.u64 t, %1; cvt.u32.u64 %0, t; }" : "=r"(a) : "l"(p));
    return a;
}
__device__ __forceinline__ void ldsm4(uint32_t* r, uint32_t addr) {
    asm volatile("ldmatrix.sync.aligned.m8n8.x4.shared.b16 {%0,%1,%2,%3}, [%4];"
                 : "=r"(r[0]), "=r"(r[1]), "=r"(r[2]), "=r"(r[3]) : "r"(addr));
}
__device__ __forceinline__ void mma16816(float* d, const uint32_t* a, const uint32_t* b) {
    asm volatile("mma.sync.aligned.m16n8k16.row.col.f32.f16.f16.f32 "
                 "{%0,%1,%2,%3}, {%4,%5,%6,%7}, {%8,%9}, {%0,%1,%2,%3};"
                 : "+f"(d[0]), "+f"(d[1]), "+f"(d[2]), "+f"(d[3])
                 : "r"(a[0]), "r"(a[1]), "r"(a[2]), "r"(a[3]), "r"(b[0]), "r"(b[1]));
}
__device__ __forceinline__ float sigmoid_f(float x) {
    return 1.0f / (1.0f + __expf(-x));
}
__device__ __forceinline__ float tanh_f(float x) {
    x = fminf(fmaxf(x, -15.0f), 15.0f);
    float t = __expf(2.0f * x);
    return __fdividef(t - 1.0f, t + 1.0f);
}
__device__ __forceinline__ uint32_t pk(float a, float b) {
    __half2 h = __floats2half2_rn(a, b);
    return *reinterpret_cast<uint32_t*>(&h);
}

// ---------------------------------------------------------------- single pack kernel
// A part: 2M items (BATCH*KDIM/8), W part: 256K items (NDIM*KDIM/8). 8 floats/thread.
#define A_ITEMS (BATCH * KDIM / 8)
#define W_ITEMS (NDIM * KDIM / 8)
__global__ void pack_all(const float* __restrict__ x, const float* __restrict__ h,
                         const float* __restrict__ w_ih, const float* __restrict__ w_hh) {
    int idx = blockIdx.x * blockDim.x + threadIdx.x;
    const float* src;
    __half* dst;
    if (idx < A_ITEMS) {
        int m = idx >> 7;                 // 128 8-float chunks per row
        int k8 = (idx & 127) << 3;
        src = (k8 < 512) ? x + (size_t)m * 512 + k8
                         : h + (size_t)m * 512 + (k8 - 512);
        dst = g_xh + (size_t)m * KDIM + k8;
    } else {
        int j = idx - A_ITEMS;
        if (j >= W_ITEMS) return;
        int np = j >> 7;                  // interleaved row n' = 4h + gate
        int k8 = (j & 127) << 3;
        int g = np & 3, hh = np >> 2;
        int srow = g * 512 + hh;
        src = (k8 < 512) ? w_ih + (size_t)srow * 512 + k8
                         : w_hh + (size_t)srow * 512 + (k8 - 512);
        dst = g_w + (size_t)np * KDIM + k8;
    }
    float4 v0 = ((const float4*)src)[0];
    float4 v1 = ((const float4*)src)[1];
    uint4 u;
    u.x = pk(v0.x, v0.y);
    u.y = pk(v0.z, v0.w);
    u.z = pk(v1.x, v1.y);
    u.w = pk(v1.z, v1.w);
    *reinterpret_cast<uint4*>(dst) = u;
}

// ---------------------------------------------------------------- fused GEMM + LSTM
__global__ void __launch_bounds__(TPB, 2)
lstm_gemm(const float* __restrict__ c_prev, float* __restrict__ out,
          const float* __restrict__ b_ih, const float* __restrict__ b_hh) {
    extern __shared__ __align__(16) char dyn[];
    __shared__ float s_bias[BN];

    const int tid = threadIdx.x;
    const int wid = tid >> 5;
    const int lid = tid & 31;
    const int mw = wid >> 2;          // 0..3 : warp M index (32 rows each)
    const int nw = wid & 3;           // 0..3 : warp N index (32 cols each)
    const int m0 = blockIdx.y * BM;
    const int n0 = blockIdx.x * BN;
    const int h0g = n0 >> 2;          // 32 hidden units per CTA

    const uint32_t dynbase = smem_u32(dyn);

    // fused bias: interleaved n' = 4h + gate
    if (tid < BN) {
        int np = n0 + tid;
        int g = np & 3, hh = np >> 2;
        s_bias[tid] = b_ih[g * 512 + hh] + b_hh[g * 512 + hh];
    }

    float acc[2][4][4];               // [mt 16-rows][nt 8-cols][frag] : 32x32 warp tile
    #pragma unroll
    for (int a = 0; a < 2; a++)
        #pragma unroll
        for (int b = 0; b < 4; b++)
            #pragma unroll
            for (int c = 0; c < 4; c++) acc[a][b][c] = 0.0f;

    // -------- per-thread loader: 2 A chunks + 2 B chunks of 16B per stage
    const int lrow = tid >> 3;        // 0..63
    const int lcc  = tid & 7;         // c16 index 0..7
    const int lswz = (lcc ^ (lrow & 7)) << 4;    // XOR swizzle (row+64 has same low3)
    const __half* gA = g_xh + (size_t)(m0 + lrow) * KDIM + lcc * 8;
    const __half* gB = g_w  + (size_t)(n0 + lrow) * KDIM + lcc * 8;
    const uint32_t sa = dynbase + lrow * ROWB + lswz;
    const uint32_t sb = sa + STAGE_A;
    const size_t GROW64 = (size_t)64 * KDIM;     // +64 rows in gmem

    #define LOAD_STAGE(OFS)                                                     \
        do {                                                                    \
            asm volatile("cp.async.cg.shared.global [%0], [%1], 16;"            \
                         :: "r"(sa + (OFS)), "l"(gA));                          \
            asm volatile("cp.async.cg.shared.global [%0], [%1], 16;"            \
                         :: "r"(sa + 64 * ROWB + (OFS)), "l"(gA + GROW64));     \
            asm volatile("cp.async.cg.shared.global [%0], [%1], 16;"            \
                         :: "r"(sb + (OFS)), "l"(gB));                          \
            asm volatile("cp.async.cg.shared.global [%0], [%1], 16;"            \
                         :: "r"(sb + 64 * ROWB + (OFS)), "l"(gB + GROW64));     \
            gA += BK; gB += BK;                                                 \
        } while (0)

    // per-warp ldsm addressing: per-q swizzled bases hoisted as INDIVIDUAL
    // scalars (never an indexable array — those spill at the 64-reg cap)
    const int arow = mw * 32 + (lid & 15);
    const uint32_t abase = dynbase + arow * ROWB;
    const int rxa = arow & 7;
    const int hia = lid >> 4;                    // col16 half
    const int bg = lid >> 3, br = lid & 7;
    const int brow = nw * 32 + (bg >> 1) * 8 + br;
    const uint32_t bbase = dynbase + STAGE_A + brow * ROWB;
    const int rxb = br;
    const int hib = bg & 1;
    const uint32_t aq0 = abase + (uint32_t)(((0 + hia) ^ rxa) << 4);
    const uint32_t aq1 = abase + (uint32_t)(((2 + hia) ^ rxa) << 4);
    const uint32_t aq2 = abase + (uint32_t)(((4 + hia) ^ rxa) << 4);
    const uint32_t aq3 = abase + (uint32_t)(((6 + hia) ^ rxa) << 4);
    const uint32_t bq0 = bbase + (uint32_t)(((0 + hib) ^ rxb) << 4);
    const uint32_t bq1 = bbase + (uint32_t)(((2 + hib) ^ rxb) << 4);
    const uint32_t bq2 = bbase + (uint32_t)(((4 + hib) ^ rxb) << 4);
    const uint32_t bq3 = bbase + (uint32_t)(((6 + hib) ^ rxb) << 4);

    #define COMPUTE_Q(SOFS, AQ, BQ)                                             \
        do {                                                                    \
            uint32_t afr[2][4], bfr[2][4];                                      \
            ldsm4(afr[0], (AQ) + (SOFS));                                       \
            ldsm4(afr[1], (AQ) + (SOFS) + 16 * ROWB);                           \
            ldsm4(bfr[0], (BQ) + (SOFS));                                       \
            ldsm4(bfr[1], (BQ) + (SOFS) + 16 * ROWB);                           \
            mma16816(acc[0][0], afr[0], &bfr[0][0]);                            \
            mma16816(acc[0][1], afr[0], &bfr[0][2]);                            \
            mma16816(acc[0][2], afr[0], &bfr[1][0]);                            \
            mma16816(acc[0][3], afr[0], &bfr[1][2]);                            \
            mma16816(acc[1][0], afr[1], &bfr[0][0]);                            \
            mma16816(acc[1][1], afr[1], &bfr[0][2]);                            \
            mma16816(acc[1][2], afr[1], &bfr[1][0]);                            \
            mma16816(acc[1][3], afr[1], &bfr[1][2]);                            \
        } while (0)

    // prologue: prefetch NST-1 stages
    LOAD_STAGE(0);
    asm volatile("cp.async.commit_group;" ::: "memory");
    LOAD_STAGE(STAGE_BYTES);
    asm volatile("cp.async.commit_group;" ::: "memory");

    // epilogue c_prev tile lives in pipeline slot 1 (free from kb=KBLK-2 on),
    // 36-float rows (144B, 16B-aligned) for cp.async
    const uint32_t c_base = dynbase + STAGE_BYTES;

    // main K loop — one barrier per iteration; loader issued after q0 so the
    // post-barrier issue burst goes to LDSM/HMMA ramp first
    uint32_t scur = 0, sload = 2 * STAGE_BYTES;
    for (int kb = 0; kb < KBLK; kb++) {
        asm volatile("cp.async.wait_group %0;" :: "n"(NST - 2) : "memory");
        __syncthreads();
        COMPUTE_Q(scur, aq0, bq0);
        if (kb < KBLK - 2) {
            LOAD_STAGE(sload);
            sload += STAGE_BYTES;
            if (sload == NST * STAGE_BYTES) sload = 0;
        } else if (kb == KBLK - 2) {
            // prefetch c_prev into slot 1 (overlaps last two K-steps)
            #pragma unroll
            for (int i = 0; i < 2; i++) {
                int idx = tid + i * TPB;         // 0..1023
                int r = idx >> 3, c16 = idx & 7;
                uint32_t saddr = c_base + r * 144 + c16 * 16;
                const float* gaddr = c_prev + (size_t)(m0 + r) * HID + h0g + c16 * 4;
                asm volatile("cp.async.cg.shared.global [%0], [%1], 16;"
                             :: "r"(saddr), "l"(gaddr));
            }
        }
        asm volatile("cp.async.commit_group;" ::: "memory");
        COMPUTE_Q(scur, aq1, bq1);
        COMPUTE_Q(scur, aq2, bq2);
        COMPUTE_Q(scur, aq3, bq3);
        scur += STAGE_BYTES;
        if (scur == NST * STAGE_BYTES) scur = 0;
    }

    // drain c_prev prefetch; all MMAs done
    asm volatile("cp.async.wait_group 0;" ::: "memory");
    __syncthreads();

    // -------- fused LSTM epilogue
    float* c_tile = (float*)(dyn + STAGE_BYTES);          // [128][36] (slot 1)
    float* hstage = (float*)dyn;                          // [128][33] (slot 0)
    float* cstage = (float*)(dyn + 2 * STAGE_BYTES);      // [128][33] (slot 2)
    const int odd = lid & 1;

    #pragma unroll
    for (int mt = 0; mt < 2; mt++) {
        const int r0 = mw * 32 + mt * 16 + (lid >> 2);
        const int rme = r0 + (odd << 3);          // even lane: r0; odd lane: r0+8
        #pragma unroll
        for (int nt = 0; nt < 4; nt++) {
            int ncol = nw * 32 + nt * 8 + 2 * (lid & 3);
            float b0 = s_bias[ncol], b1 = s_bias[ncol + 1];
            float v00 = acc[mt][nt][0] + b0;     // row r0,   col ncol
            float v01 = acc[mt][nt][1] + b1;     // row r0,   col ncol+1
            float v10 = acc[mt][nt][2] + b0;     // row r0+8, col ncol
            float v11 = acc[mt][nt][3] + b1;     // row r0+8, col ncol+1
            // even lane holds (i,f); odd lane holds (g,o) of the same hidden unit
            float w00 = __shfl_xor_sync(0xffffffffu, v00, 1);
            float w01 = __shfl_xor_sync(0xffffffffu, v01, 1);
            float w10 = __shfl_xor_sync(0xffffffffu, v10, 1);
            float w11 = __shfl_xor_sync(0xffffffffu, v11, 1);
            // even lane computes row r0: i=v00 f=v01 g=w00 o=w01
            // odd  lane computes row r0+8: i=w10 f=w11 g=v10 o=v11
            float gi = odd ? w10 : v00;
            float gf = odd ? w11 : v01;
            float gg = odd ? v10 : w00;
            float go = odd ? v11 : w01;
            int hl = ncol >> 2;
            float ia = sigmoid_f(gi), fa = sigmoid_f(gf);
            float ga = tanh_f(gg),    oa = sigmoid_f(go);
            float cp = c_tile[rme * 36 + hl];
            float cn = fa * cp + ia * ga;
            cstage[rme * 33 + hl] = cn;
            hstage[rme * 33 + hl] = oa * tanh_f(cn);
        }
    }
    __syncthreads();

    // coalesced writeout: h_new then c_new (128B segments per row)
    for (int i = tid; i < 128 * 32; i += TPB) {
        int r = i >> 5, hh = i & 31;
        size_t go = (size_t)(m0 + r) * HID + h0g + hh;
        out[go] = hstage[r * 33 + hh];
        out[(size_t)BATCH * HID + go] = cstage[r * 33 + hh];
    }
}

// ---------------------------------------------------------------- launch
extern "C" void kernel_launch(void* const* d_in, const int* in_sizes, int n_in,
                              void* d_out, int out_size) {
    const float* x      = (const float*)d_in[0];
    const float* h_prev = (const float*)d_in[1];
    const float* c_prev = (const float*)d_in[2];
    const float* w_ih   = (const float*)d_in[3];
    const float* w_hh   = (const float*)d_in[4];
    const float* b_ih   = (const float*)d_in[5];
    const float* b_hh   = (const float*)d_in[6];
    float* out = (float*)d_out;

    pack_all<<<(A_ITEMS + W_ITEMS + 255) / 256, 256>>>(x, h_prev, w_ih, w_hh);

    cudaFuncSetAttribute(lstm_gemm, cudaFuncAttributeMaxDynamicSharedMemorySize, SMEM_DYN);
    dim3 grid(NDIM / BN, BATCH / BM);   // (16, 128)
    lstm_gemm<<<grid, TPB, SMEM_DYN>>>(c_prev, out, b_ih, b_hh);
}